// round 9
// baseline (speedup 1.0000x reference)
#include <cuda_runtime.h>
#include <cstdint>

#define NB      8
#define NCH     3
#define IMG     1024
#define PATCH   128
#define DPOS    256
#define KSEL    16
#define NSAMP   500
#define HGRID   16
#define WGRID   16
#define NKB     4          // k blocks
#define KPB     4          // k per block

typedef unsigned long long ull;

// Persistent device scratch (zero-init at load; build_kernel re-zeroes
// d_counts after consuming it -> clean state for every graph replay).
__device__ int  d_counts[NB][KSEL][DPOS];
__device__ int  d_koff[NB][NKB + 1];
__device__ int  d_kmid[NB][NKB];            // interior/boundary split point
__device__ int  d_kpos[NB][NKB * DPOS];     // flat offset ii*64*1024 + iw*64
__device__ __align__(32) ull d_kwt[NB][NKB * DPOS][KPB];  // packed {w,w} f32x2

// ---------------------------------------------------------------------------
// Threefry-2x32 (20 rounds), JAX partitionable layout:
//   bits[f] = o0 ^ o1 of E(key=(0,42), ctr=(hi=0, lo=f))
// ---------------------------------------------------------------------------
__device__ __forceinline__ uint32_t threefry_bits(uint32_t ctr) {
    const uint32_t K0 = 0u;
    const uint32_t K1 = 42u;
    const uint32_t K2 = 0x1BD11BDAu ^ K0 ^ K1;
    uint32_t x0 = K0;
    uint32_t x1 = ctr + K1;
#define TFR(r) { x0 += x1; x1 = __funnelshift_l(x1, x1, (r)); x1 ^= x0; }
    TFR(13) TFR(15) TFR(26) TFR(6)
    x0 += K1; x1 += K2 + 1u;
    TFR(17) TFR(29) TFR(16) TFR(24)
    x0 += K2; x1 += K0 + 2u;
    TFR(13) TFR(15) TFR(26) TFR(6)
    x0 += K0; x1 += K1 + 3u;
    TFR(17) TFR(29) TFR(16) TFR(24)
    x0 += K1; x1 += K2 + 4u;
    TFR(13) TFR(15) TFR(26) TFR(6)
    x0 += K2; x1 += K0 + 5u;
#undef TFR
    return x0 ^ x1;
}

__device__ __forceinline__ float jax_normal(uint32_t f) {
    uint32_t bits = threefry_bits(f);
    float fl = __uint_as_float((bits >> 9) | 0x3f800000u) - 1.0f;  // [0,1)
    const float lo = -0.99999994f;
    float u = fl * 2.0f + lo;
    u = fmaxf(lo, u);
    return __uint_as_float(0x3fb504f3u) * erfinvf(u);   // sqrt(2)*erfinv
}

// monotone float -> sortable u32 (strictly order-preserving)
__device__ __forceinline__ uint32_t fkey(float v) {
    uint32_t u = __float_as_uint(v);
    return u ^ (uint32_t)(((int)u >> 31) | 0x80000000);
}

// ---------------------------------------------------------------------------
// Kernel 1: perturbed top-K counting; fused normalization; 1 sample/warp,
// REDUX-based selection. grid = (125, NB), block = 128 (4 warps).
// ---------------------------------------------------------------------------
__global__ void indicator_kernel(const float* __restrict__ scores) {
    __shared__ float s_sh[DPOS];
    __shared__ float red[64];
    int b = blockIdx.y;
    int t = threadIdx.x;
    int warp = t >> 5, lane = t & 31;

    // per-batch min/max normalize (redundant per block; trivial)
    float v0 = __ldg(scores + b * DPOS + t);
    float v1 = __ldg(scores + b * DPOS + 128 + t);
    float mn = fminf(v0, v1), mx = fmaxf(v0, v1);
#pragma unroll
    for (int off = 16; off; off >>= 1) {
        mn = fminf(mn, __shfl_down_sync(0xffffffffu, mn, off));
        mx = fmaxf(mx, __shfl_down_sync(0xffffffffu, mx, off));
    }
    if (lane == 0) { red[warp] = mn; red[32 + warp] = mx; }
    __syncthreads();
    if (t == 0) {
        float m0 = red[0], m1 = red[32];
#pragma unroll
        for (int j = 1; j < 4; j++) { m0 = fminf(m0, red[j]); m1 = fmaxf(m1, red[32 + j]); }
        red[0] = m0; red[32] = m1;
    }
    __syncthreads();
    mn = red[0]; mx = red[32];
    float den = (mx - mn) + 1e-5f;
    s_sh[t]       = __fdiv_rn(v0 - mn, den);
    s_sh[t + 128] = __fdiv_rn(v1 - mn, den);
    __syncthreads();

    int sample = blockIdx.x * 4 + warp;            // 0..499
    uint32_t base = (uint32_t)((b * NSAMP + sample) * DPOS);

    uint32_t ka[8];
#pragma unroll
    for (int j = 0; j < 8; j++) {
        int pos = j * 32 + lane;
        float z = jax_normal(base + (uint32_t)pos);
        ka[j] = fkey(__fadd_rn(s_sh[pos], __fmul_rn(z, 0.05f)));
    }

    int sel = 0;
    for (int it = 0; it < KSEL; it++) {
        uint32_t bk = 0u;
        int bp = 0x7fffffff;
#pragma unroll
        for (int j = 0; j < 8; j++) {
            int pos = j * 32 + lane;
            if (ka[j] > bk) { bk = ka[j]; bp = pos; }
        }
        uint32_t m = __reduce_max_sync(0xffffffffu, bk);
        unsigned cand = (bk == m) ? (unsigned)bp : 0x7fffffffu;
        int w = (int)__reduce_min_sync(0xffffffffu, cand);
        int sj = w >> 5;
        if (lane == (w & 31)) {
#pragma unroll
            for (int j = 0; j < 8; j++) if (j == sj) ka[j] = 0u;
        }
        if (lane == it) sel = w;
    }

    // rank = index order among the 16 selections
    int r = 0;
#pragma unroll
    for (int j = 0; j < KSEL; j++) {
        int o = __shfl_sync(0xffffffffu, sel, j);
        if (o < sel) r++;
    }
    if (lane < KSEL) atomicAdd(&d_counts[b][r][sel], 1);
}

// ---------------------------------------------------------------------------
// Kernel 2: build per-(b, kblock) sub-lists, interior entries first then
// boundary; entries stored as flat image offsets. Re-zeroes d_counts.
// grid = NB, block = 256 (thread = position).
// ---------------------------------------------------------------------------
__global__ void build_kernel() {
    __shared__ int wcnt_i[8], wcnt_b[8];
    __shared__ int s_base;
    int b = blockIdx.x, t = threadIdx.x;
    int warp = t >> 5, lane = t & 31;

    int cnt[KSEL];
#pragma unroll
    for (int k = 0; k < KSEL; k++) { cnt[k] = d_counts[b][k][t]; d_counts[b][k][t] = 0; }

    int ii = t >> 4, iw = t & 15;
    bool isBnd = (ii == 0) | (ii == 15) | (iw == 0) | (iw == 15);
    int flat = ii * 64 * 1024 + iw * 64;

    if (t == 0) s_base = 0;
    __syncthreads();

#pragma unroll
    for (int kb = 0; kb < NKB; kb++) {
        int any = cnt[4 * kb] | cnt[4 * kb + 1] | cnt[4 * kb + 2] | cnt[4 * kb + 3];
        unsigned mi = __ballot_sync(0xffffffffu, (any != 0) && !isBnd);
        unsigned mb = __ballot_sync(0xffffffffu, (any != 0) && isBnd);
        if (lane == 0) { wcnt_i[warp] = __popc(mi); wcnt_b[warp] = __popc(mb); }
        __syncthreads();
        int basei = 0, ni = 0, baseb = 0, nb = 0;
#pragma unroll
        for (int wj = 0; wj < 8; wj++) {
            int wci = wcnt_i[wj], wcb = wcnt_b[wj];
            if (wj < warp) { basei += wci; baseb += wcb; }
            ni += wci; nb += wcb;
        }
        int base = s_base;
        if (any) {
            int slot;
            if (!isBnd) slot = base + basei + __popc(mi & ((1u << lane) - 1u));
            else        slot = base + ni + baseb + __popc(mb & ((1u << lane) - 1u));
            d_kpos[b][slot] = flat;
#pragma unroll
            for (int j = 0; j < KPB; j++) {
                float w = __fdiv_rn((float)cnt[4 * kb + j], 500.0f);
                uint32_t wb = __float_as_uint(w);
                d_kwt[b][slot][j] = ((ull)wb << 32) | (ull)wb;
            }
        }
        if (t == 0) { d_koff[b][kb] = base; d_kmid[b][kb] = base + ni; }
        __syncthreads();
        if (t == 0) s_base = base + ni + nb;
        __syncthreads();
    }
    if (t == 0) d_koff[b][NKB] = s_base;
}

// ---------------------------------------------------------------------------
// Kernel 3: patch assembly. 4 k-block phases; interior entries run with
// zero bounds logic (1 IADD of a pre-multiplied flat offset), boundary
// entries keep checks. grid = (32 pt, 3 c, 8 b), block = 128.
// ---------------------------------------------------------------------------
__device__ __forceinline__ ull fma2(ull a, ull b, ull c) {
    ull d;
    asm("fma.rn.f32x2 %0, %1, %2, %3;" : "=l"(d) : "l"(a), "l"(b), "l"(c));
    return d;
}

__global__ void __launch_bounds__(128) assemble_kernel(const float* __restrict__ x,
                                                       float* __restrict__ out) {
    __shared__ int s_off[NKB + 1];
    __shared__ int s_mid[NKB];
    __shared__ int s_pos[NKB * DPOS];
    __shared__ alignas(32) ull s_wt[NKB * DPOS][KPB];

    int pt = blockIdx.x;          // 0..31
    int c  = blockIdx.y;
    int b  = blockIdx.z;
    int t  = threadIdx.x;

    int ntot = d_koff[b][NKB];
    if (t <= NKB) s_off[t] = d_koff[b][t];
    if (t < NKB)  s_mid[t] = d_kmid[b][t];
    for (int i = t; i < ntot; i += 128) s_pos[i] = d_kpos[b][i];
    {   // 128-bit staging of weight table
        const ulonglong2* src = (const ulonglong2*)&d_kwt[b][0][0];
        ulonglong2* dst = (ulonglong2*)&s_wt[0][0];
        int n2 = ntot * 2;
        for (int i = t; i < n2; i += 128) dst[i] = src[i];
    }
    __syncthreads();

    int qt = t & 63;              // q pair: q = 2qt, 2qt+1
    int pr = t >> 6;              // 0..1
    int p0 = pt * 4 + pr * 2;     // rows p0, p0+1
    int qc = 2 * qt - 32;         // window col offset (even)
    int pc0 = p0 - 32;

    const float* xb  = x + ((size_t)(b * NCH + c) << 20);
    const float* xb2 = xb + ((ptrdiff_t)pc0 << 10) + qc;   // interior base

#pragma unroll
    for (int kb = 0; kb < NKB; kb++) {
        int e    = s_off[kb];
        int mid  = s_mid[kb];
        int eend = s_off[kb + 1];

        ull acc0[KPB], acc1[KPB];
#pragma unroll
        for (int j = 0; j < KPB; j++) { acc0[j] = 0ull; acc1[j] = 0ull; }

        // ---- interior: unconditional loads ----
#pragma unroll 1
        for (; e + 2 <= mid; e += 2) {
            const float* pa = xb2 + s_pos[e];
            const float* pb = xb2 + s_pos[e + 1];
            ull vA0 = *(const ull*)pa;
            ull vA1 = *(const ull*)(pa + IMG);
            ull vB0 = *(const ull*)pb;
            ull vB1 = *(const ull*)(pb + IMG);
            ulonglong2 wA0 = *(const ulonglong2*)&s_wt[e][0];
            ulonglong2 wA1 = *(const ulonglong2*)&s_wt[e][2];
            ulonglong2 wB0 = *(const ulonglong2*)&s_wt[e + 1][0];
            ulonglong2 wB1 = *(const ulonglong2*)&s_wt[e + 1][2];
            acc0[0] = fma2(wA0.x, vA0, acc0[0]); acc1[0] = fma2(wA0.x, vA1, acc1[0]);
            acc0[1] = fma2(wA0.y, vA0, acc0[1]); acc1[1] = fma2(wA0.y, vA1, acc1[1]);
            acc0[2] = fma2(wA1.x, vA0, acc0[2]); acc1[2] = fma2(wA1.x, vA1, acc1[2]);
            acc0[3] = fma2(wA1.y, vA0, acc0[3]); acc1[3] = fma2(wA1.y, vA1, acc1[3]);
            acc0[0] = fma2(wB0.x, vB0, acc0[0]); acc1[0] = fma2(wB0.x, vB1, acc1[0]);
            acc0[1] = fma2(wB0.y, vB0, acc0[1]); acc1[1] = fma2(wB0.y, vB1, acc1[1]);
            acc0[2] = fma2(wB1.x, vB0, acc0[2]); acc1[2] = fma2(wB1.x, vB1, acc1[2]);
            acc0[3] = fma2(wB1.y, vB0, acc0[3]); acc1[3] = fma2(wB1.y, vB1, acc1[3]);
        }
        for (; e < mid; e++) {
            const float* pa = xb2 + s_pos[e];
            ull v0 = *(const ull*)pa;
            ull v1 = *(const ull*)(pa + IMG);
            ulonglong2 w0 = *(const ulonglong2*)&s_wt[e][0];
            ulonglong2 w1 = *(const ulonglong2*)&s_wt[e][2];
            acc0[0] = fma2(w0.x, v0, acc0[0]); acc1[0] = fma2(w0.x, v1, acc1[0]);
            acc0[1] = fma2(w0.y, v0, acc0[1]); acc1[1] = fma2(w0.y, v1, acc1[1]);
            acc0[2] = fma2(w1.x, v0, acc0[2]); acc1[2] = fma2(w1.x, v1, acc1[2]);
            acc0[3] = fma2(w1.y, v0, acc0[3]); acc1[3] = fma2(w1.y, v1, acc1[3]);
        }

        // ---- boundary: bounds-checked ----
#pragma unroll 1
        for (; e < eend; e++) {
            int flat = s_pos[e];
            int col = (flat & 1023) + qc;
            int rw0 = (flat >> 10) + pc0;
            bool cok = (unsigned)col < 1024u;
            ull v0 = 0ull, v1 = 0ull;
            const float* pa = xb + ((size_t)rw0 << 10) + col;
            if (cok && (unsigned)rw0 < 1024u)       v0 = *(const ull*)pa;
            if (cok && (unsigned)(rw0 + 1) < 1024u) v1 = *(const ull*)(pa + IMG);
            ulonglong2 w0 = *(const ulonglong2*)&s_wt[e][0];
            ulonglong2 w1 = *(const ulonglong2*)&s_wt[e][2];
            acc0[0] = fma2(w0.x, v0, acc0[0]); acc1[0] = fma2(w0.x, v1, acc1[0]);
            acc0[1] = fma2(w0.y, v0, acc0[1]); acc1[1] = fma2(w0.y, v1, acc1[1]);
            acc0[2] = fma2(w1.x, v0, acc0[2]); acc1[2] = fma2(w1.x, v1, acc1[2]);
            acc0[3] = fma2(w1.y, v0, acc0[3]); acc1[3] = fma2(w1.y, v1, acc1[3]);
        }

#pragma unroll
        for (int j = 0; j < KPB; j++) {
            int k = kb * KPB + j;
            float* op = out + (((size_t)((b * KSEL + k) * NCH + c)) << 14)
                            + ((size_t)p0 << 7) + 2 * qt;
            *(ull*)op           = acc0[j];
            *(ull*)(op + PATCH) = acc1[j];
        }
    }
}

// ---------------------------------------------------------------------------
extern "C" void kernel_launch(void* const* d_in, const int* in_sizes, int n_in,
                              void* d_out, int out_size) {
    const float* x      = (const float*)d_in[0];
    const float* scores = (const float*)d_in[1];
    if (n_in >= 2 && in_sizes[0] == NB * HGRID * WGRID) {
        const float* tmp = x; x = scores; scores = tmp;
    }
    float* out = (float*)d_out;

    indicator_kernel<<<dim3(125, NB), 128>>>(scores);
    build_kernel<<<NB, 256>>>();
    assemble_kernel<<<dim3(32, NCH, NB), 128>>>(x, out);
}

// round 11
// speedup vs baseline: 1.5779x; 1.5779x over previous
#include <cuda_runtime.h>
#include <cstdint>

#define NB      8
#define NCH     3
#define IMG     1024
#define PATCH   128
#define DPOS    256
#define KSEL    16
#define NSAMP   500
#define HGRID   16
#define WGRID   16
#define NKB     4          // k blocks
#define KPB     4          // k per block

typedef unsigned long long ull;

// Persistent device scratch (zero-init at load; build_kernel re-zeroes
// d_counts after consuming it -> clean state for every graph replay).
__device__ int  d_counts[NB][KSEL][DPOS];
__device__ int  d_koff[NB][NKB + 1];
__device__ int  d_kmid[NB][NKB];            // interior/boundary split point
__device__ int  d_kpos[NB][NKB * DPOS];     // flat offset ii*64*1024 + iw*64
__device__ __align__(32) ull d_kwt[NB][NKB * DPOS][KPB];  // packed {w,w} f32x2

// ---------------------------------------------------------------------------
// Threefry-2x32 (20 rounds), JAX partitionable layout:
//   bits[f] = o0 ^ o1 of E(key=(0,42), ctr=(hi=0, lo=f))
// ---------------------------------------------------------------------------
__device__ __forceinline__ uint32_t threefry_bits(uint32_t ctr) {
    const uint32_t K0 = 0u;
    const uint32_t K1 = 42u;
    const uint32_t K2 = 0x1BD11BDAu ^ K0 ^ K1;
    uint32_t x0 = K0;
    uint32_t x1 = ctr + K1;
#define TFR(r) { x0 += x1; x1 = __funnelshift_l(x1, x1, (r)); x1 ^= x0; }
    TFR(13) TFR(15) TFR(26) TFR(6)
    x0 += K1; x1 += K2 + 1u;
    TFR(17) TFR(29) TFR(16) TFR(24)
    x0 += K2; x1 += K0 + 2u;
    TFR(13) TFR(15) TFR(26) TFR(6)
    x0 += K0; x1 += K1 + 3u;
    TFR(17) TFR(29) TFR(16) TFR(24)
    x0 += K1; x1 += K2 + 4u;
    TFR(13) TFR(15) TFR(26) TFR(6)
    x0 += K2; x1 += K0 + 5u;
#undef TFR
    return x0 ^ x1;
}

__device__ __forceinline__ float jax_normal(uint32_t f) {
    uint32_t bits = threefry_bits(f);
    float fl = __uint_as_float((bits >> 9) | 0x3f800000u) - 1.0f;  // [0,1)
    const float lo = -0.99999994f;
    float u = fl * 2.0f + lo;
    u = fmaxf(lo, u);
    return __uint_as_float(0x3fb504f3u) * erfinvf(u);   // sqrt(2)*erfinv
}

// monotone float -> sortable u32 (strictly order-preserving)
__device__ __forceinline__ uint32_t fkey(float v) {
    uint32_t u = __float_as_uint(v);
    return u ^ (uint32_t)(((int)u >> 31) | 0x80000000);
}

// ---------------------------------------------------------------------------
// Kernel 1: perturbed top-K counting; fused normalization; 1 sample/warp,
// REDUX-based selection. grid = (125, NB), block = 128 (4 warps).
// ---------------------------------------------------------------------------
__global__ void indicator_kernel(const float* __restrict__ scores) {
    __shared__ float s_sh[DPOS];
    __shared__ float red[64];
    int b = blockIdx.y;
    int t = threadIdx.x;
    int warp = t >> 5, lane = t & 31;

    // per-batch min/max normalize (redundant per block; trivial)
    float v0 = __ldg(scores + b * DPOS + t);
    float v1 = __ldg(scores + b * DPOS + 128 + t);
    float mn = fminf(v0, v1), mx = fmaxf(v0, v1);
#pragma unroll
    for (int off = 16; off; off >>= 1) {
        mn = fminf(mn, __shfl_down_sync(0xffffffffu, mn, off));
        mx = fmaxf(mx, __shfl_down_sync(0xffffffffu, mx, off));
    }
    if (lane == 0) { red[warp] = mn; red[32 + warp] = mx; }
    __syncthreads();
    if (t == 0) {
        float m0 = red[0], m1 = red[32];
#pragma unroll
        for (int j = 1; j < 4; j++) { m0 = fminf(m0, red[j]); m1 = fmaxf(m1, red[32 + j]); }
        red[0] = m0; red[32] = m1;
    }
    __syncthreads();
    mn = red[0]; mx = red[32];
    float den = (mx - mn) + 1e-5f;
    s_sh[t]       = __fdiv_rn(v0 - mn, den);
    s_sh[t + 128] = __fdiv_rn(v1 - mn, den);
    __syncthreads();

    int sample = blockIdx.x * 4 + warp;            // 0..499
    uint32_t base = (uint32_t)((b * NSAMP + sample) * DPOS);

    uint32_t ka[8];
#pragma unroll
    for (int j = 0; j < 8; j++) {
        int pos = j * 32 + lane;
        float z = jax_normal(base + (uint32_t)pos);
        ka[j] = fkey(__fadd_rn(s_sh[pos], __fmul_rn(z, 0.05f)));
    }

    int sel = 0;
    for (int it = 0; it < KSEL; it++) {
        uint32_t bk = 0u;
        int bp = 0x7fffffff;
#pragma unroll
        for (int j = 0; j < 8; j++) {
            int pos = j * 32 + lane;
            if (ka[j] > bk) { bk = ka[j]; bp = pos; }
        }
        uint32_t m = __reduce_max_sync(0xffffffffu, bk);
        unsigned cand = (bk == m) ? (unsigned)bp : 0x7fffffffu;
        int w = (int)__reduce_min_sync(0xffffffffu, cand);
        int sj = w >> 5;
        if (lane == (w & 31)) {
#pragma unroll
            for (int j = 0; j < 8; j++) if (j == sj) ka[j] = 0u;
        }
        if (lane == it) sel = w;
    }

    // rank = index order among the 16 selections
    int r = 0;
#pragma unroll
    for (int j = 0; j < KSEL; j++) {
        int o = __shfl_sync(0xffffffffu, sel, j);
        if (o < sel) r++;
    }
    if (lane < KSEL) atomicAdd(&d_counts[b][r][sel], 1);
}

// ---------------------------------------------------------------------------
// Kernel 2: build per-(b, kblock) sub-lists, interior entries first then
// boundary; entries stored as flat image offsets. Re-zeroes d_counts.
// grid = NB, block = 256 (thread = position).
// ---------------------------------------------------------------------------
__global__ void build_kernel() {
    __shared__ int wcnt_i[8], wcnt_b[8];
    __shared__ int s_base;
    int b = blockIdx.x, t = threadIdx.x;
    int warp = t >> 5, lane = t & 31;

    int cnt[KSEL];
#pragma unroll
    for (int k = 0; k < KSEL; k++) { cnt[k] = d_counts[b][k][t]; d_counts[b][k][t] = 0; }

    int ii = t >> 4, iw = t & 15;
    bool isBnd = (ii == 0) | (ii == 15) | (iw == 0) | (iw == 15);
    int flat = ii * 64 * 1024 + iw * 64;

    if (t == 0) s_base = 0;
    __syncthreads();

#pragma unroll
    for (int kb = 0; kb < NKB; kb++) {
        int any = cnt[4 * kb] | cnt[4 * kb + 1] | cnt[4 * kb + 2] | cnt[4 * kb + 3];
        unsigned mi = __ballot_sync(0xffffffffu, (any != 0) && !isBnd);
        unsigned mb = __ballot_sync(0xffffffffu, (any != 0) && isBnd);
        if (lane == 0) { wcnt_i[warp] = __popc(mi); wcnt_b[warp] = __popc(mb); }
        __syncthreads();
        int basei = 0, ni = 0, baseb = 0, nb = 0;
#pragma unroll
        for (int wj = 0; wj < 8; wj++) {
            int wci = wcnt_i[wj], wcb = wcnt_b[wj];
            if (wj < warp) { basei += wci; baseb += wcb; }
            ni += wci; nb += wcb;
        }
        int base = s_base;
        if (any) {
            int slot;
            if (!isBnd) slot = base + basei + __popc(mi & ((1u << lane) - 1u));
            else        slot = base + ni + baseb + __popc(mb & ((1u << lane) - 1u));
            d_kpos[b][slot] = flat;
#pragma unroll
            for (int j = 0; j < KPB; j++) {
                float w = __fdiv_rn((float)cnt[4 * kb + j], 500.0f);
                uint32_t wb = __float_as_uint(w);
                d_kwt[b][slot][j] = ((ull)wb << 32) | (ull)wb;
            }
        }
        if (t == 0) { d_koff[b][kb] = base; d_kmid[b][kb] = base + ni; }
        __syncthreads();
        if (t == 0) s_base = base + ni + nb;
        __syncthreads();
    }
    if (t == 0) d_koff[b][NKB] = s_base;
}

// ---------------------------------------------------------------------------
// Kernel 3: patch assembly. 4 k-block phases; interior entries run with
// zero bounds logic and a 4-entry unroll issuing 8 independent LDG.64s
// up-front (MLP=8) before the FMA chain. grid = (32 pt, 3 c, 8 b), 128 thr.
// ---------------------------------------------------------------------------
__device__ __forceinline__ ull fma2(ull a, ull b, ull c) {
    ull d;
    asm("fma.rn.f32x2 %0, %1, %2, %3;" : "=l"(d) : "l"(a), "l"(b), "l"(c));
    return d;
}

__global__ void __launch_bounds__(128) assemble_kernel(const float* __restrict__ x,
                                                       float* __restrict__ out) {
    __shared__ int s_off[NKB + 1];
    __shared__ int s_mid[NKB];
    __shared__ int s_pos[NKB * DPOS];
    __shared__ alignas(32) ull s_wt[NKB * DPOS][KPB];

    int pt = blockIdx.x;          // 0..31
    int c  = blockIdx.y;
    int b  = blockIdx.z;
    int t  = threadIdx.x;

    int ntot = d_koff[b][NKB];
    if (t <= NKB) s_off[t] = d_koff[b][t];
    if (t < NKB)  s_mid[t] = d_kmid[b][t];
    for (int i = t; i < ntot; i += 128) s_pos[i] = d_kpos[b][i];
    {   // 128-bit staging of weight table
        const ulonglong2* src = (const ulonglong2*)&d_kwt[b][0][0];
        ulonglong2* dst = (ulonglong2*)&s_wt[0][0];
        int n2 = ntot * 2;
        for (int i = t; i < n2; i += 128) dst[i] = src[i];
    }
    __syncthreads();

    int qt = t & 63;              // q pair: q = 2qt, 2qt+1
    int pr = t >> 6;              // 0..1
    int p0 = pt * 4 + pr * 2;     // rows p0, p0+1
    int qc = 2 * qt - 32;         // window col offset (even)
    int pc0 = p0 - 32;

    const float* xb  = x + ((size_t)(b * NCH + c) << 20);
    const float* xb2 = xb + ((ptrdiff_t)pc0 << 10) + qc;   // interior base

#pragma unroll
    for (int kb = 0; kb < NKB; kb++) {
        int e    = s_off[kb];
        int mid  = s_mid[kb];
        int eend = s_off[kb + 1];

        ull acc0[KPB], acc1[KPB];
#pragma unroll
        for (int j = 0; j < KPB; j++) { acc0[j] = 0ull; acc1[j] = 0ull; }

        // ---- interior: unconditional loads, 4 entries / 8 LDGs in flight ----
#pragma unroll 1
        for (; e + 4 <= mid; e += 4) {
            const float* pa = xb2 + s_pos[e];
            const float* pb = xb2 + s_pos[e + 1];
            const float* pc = xb2 + s_pos[e + 2];
            const float* pd = xb2 + s_pos[e + 3];
            ull vA0 = *(const ull*)pa;
            ull vB0 = *(const ull*)pb;
            ull vC0 = *(const ull*)pc;
            ull vD0 = *(const ull*)pd;
            ull vA1 = *(const ull*)(pa + IMG);
            ull vB1 = *(const ull*)(pb + IMG);
            ull vC1 = *(const ull*)(pc + IMG);
            ull vD1 = *(const ull*)(pd + IMG);
            ulonglong2 wA0 = *(const ulonglong2*)&s_wt[e][0];
            ulonglong2 wA1 = *(const ulonglong2*)&s_wt[e][2];
            ulonglong2 wB0 = *(const ulonglong2*)&s_wt[e + 1][0];
            ulonglong2 wB1 = *(const ulonglong2*)&s_wt[e + 1][2];
            ulonglong2 wC0 = *(const ulonglong2*)&s_wt[e + 2][0];
            ulonglong2 wC1 = *(const ulonglong2*)&s_wt[e + 2][2];
            ulonglong2 wD0 = *(const ulonglong2*)&s_wt[e + 3][0];
            ulonglong2 wD1 = *(const ulonglong2*)&s_wt[e + 3][2];
            acc0[0] = fma2(wA0.x, vA0, acc0[0]); acc1[0] = fma2(wA0.x, vA1, acc1[0]);
            acc0[1] = fma2(wA0.y, vA0, acc0[1]); acc1[1] = fma2(wA0.y, vA1, acc1[1]);
            acc0[2] = fma2(wA1.x, vA0, acc0[2]); acc1[2] = fma2(wA1.x, vA1, acc1[2]);
            acc0[3] = fma2(wA1.y, vA0, acc0[3]); acc1[3] = fma2(wA1.y, vA1, acc1[3]);
            acc0[0] = fma2(wB0.x, vB0, acc0[0]); acc1[0] = fma2(wB0.x, vB1, acc1[0]);
            acc0[1] = fma2(wB0.y, vB0, acc0[1]); acc1[1] = fma2(wB0.y, vB1, acc1[1]);
            acc0[2] = fma2(wB1.x, vB0, acc0[2]); acc1[2] = fma2(wB1.x, vB1, acc1[2]);
            acc0[3] = fma2(wB1.y, vB0, acc0[3]); acc1[3] = fma2(wB1.y, vB1, acc1[3]);
            acc0[0] = fma2(wC0.x, vC0, acc0[0]); acc1[0] = fma2(wC0.x, vC1, acc1[0]);
            acc0[1] = fma2(wC0.y, vC0, acc0[1]); acc1[1] = fma2(wC0.y, vC1, acc1[1]);
            acc0[2] = fma2(wC1.x, vC0, acc0[2]); acc1[2] = fma2(wC1.x, vC1, acc1[2]);
            acc0[3] = fma2(wC1.y, vC0, acc0[3]); acc1[3] = fma2(wC1.y, vC1, acc1[3]);
            acc0[0] = fma2(wD0.x, vD0, acc0[0]); acc1[0] = fma2(wD0.x, vD1, acc1[0]);
            acc0[1] = fma2(wD0.y, vD0, acc0[1]); acc1[1] = fma2(wD0.y, vD1, acc1[1]);
            acc0[2] = fma2(wD1.x, vD0, acc0[2]); acc1[2] = fma2(wD1.x, vD1, acc1[2]);
            acc0[3] = fma2(wD1.y, vD0, acc0[3]); acc1[3] = fma2(wD1.y, vD1, acc1[3]);
        }
#pragma unroll 1
        for (; e < mid; e++) {
            const float* pa = xb2 + s_pos[e];
            ull v0 = *(const ull*)pa;
            ull v1 = *(const ull*)(pa + IMG);
            ulonglong2 w0 = *(const ulonglong2*)&s_wt[e][0];
            ulonglong2 w1 = *(const ulonglong2*)&s_wt[e][2];
            acc0[0] = fma2(w0.x, v0, acc0[0]); acc1[0] = fma2(w0.x, v1, acc1[0]);
            acc0[1] = fma2(w0.y, v0, acc0[1]); acc1[1] = fma2(w0.y, v1, acc1[1]);
            acc0[2] = fma2(w1.x, v0, acc0[2]); acc1[2] = fma2(w1.x, v1, acc1[2]);
            acc0[3] = fma2(w1.y, v0, acc0[3]); acc1[3] = fma2(w1.y, v1, acc1[3]);
        }

        // ---- boundary: bounds-checked ----
#pragma unroll 1
        for (; e < eend; e++) {
            int flat = s_pos[e];
            int col = (flat & 1023) + qc;
            int rw0 = (flat >> 10) + pc0;
            bool cok = (unsigned)col < 1024u;
            ull v0 = 0ull, v1 = 0ull;
            const float* pa = xb + ((size_t)rw0 << 10) + col;
            if (cok && (unsigned)rw0 < 1024u)       v0 = *(const ull*)pa;
            if (cok && (unsigned)(rw0 + 1) < 1024u) v1 = *(const ull*)(pa + IMG);
            ulonglong2 w0 = *(const ulonglong2*)&s_wt[e][0];
            ulonglong2 w1 = *(const ulonglong2*)&s_wt[e][2];
            acc0[0] = fma2(w0.x, v0, acc0[0]); acc1[0] = fma2(w0.x, v1, acc1[0]);
            acc0[1] = fma2(w0.y, v0, acc0[1]); acc1[1] = fma2(w0.y, v1, acc1[1]);
            acc0[2] = fma2(w1.x, v0, acc0[2]); acc1[2] = fma2(w1.x, v1, acc1[2]);
            acc0[3] = fma2(w1.y, v0, acc0[3]); acc1[3] = fma2(w1.y, v1, acc1[3]);
        }

#pragma unroll
        for (int j = 0; j < KPB; j++) {
            int k = kb * KPB + j;
            float* op = out + (((size_t)((b * KSEL + k) * NCH + c)) << 14)
                            + ((size_t)p0 << 7) + 2 * qt;
            *(ull*)op           = acc0[j];
            *(ull*)(op + PATCH) = acc1[j];
        }
    }
}

// ---------------------------------------------------------------------------
extern "C" void kernel_launch(void* const* d_in, const int* in_sizes, int n_in,
                              void* d_out, int out_size) {
    const float* x      = (const float*)d_in[0];
    const float* scores = (const float*)d_in[1];
    if (n_in >= 2 && in_sizes[0] == NB * HGRID * WGRID) {
        const float* tmp = x; x = scores; scores = tmp;
    }
    float* out = (float*)d_out;

    indicator_kernel<<<dim3(125, NB), 128>>>(scores);
    build_kernel<<<NB, 256>>>();
    assemble_kernel<<<dim3(32, NCH, NB), 128>>>(x, out);
}

// round 12
// speedup vs baseline: 1.6531x; 1.0476x over previous
#include <cuda_runtime.h>
#include <cstdint>

#define NB      8
#define NCH     3
#define IMG     1024
#define PATCH   128
#define DPOS    256
#define KSEL    16
#define NSAMP   500
#define HGRID   16
#define WGRID   16
#define NKB     4          // k blocks
#define KPB     4          // k per block
#define NBLK    (32 * NCH * NB)   // assemble grid size = 768

typedef unsigned long long ull;

// Persistent device scratch (zero-init at load; the LAST assemble block
// re-zeroes d_counts and resets d_done -> clean state every graph replay).
__device__ __align__(16) int d_counts[NB][KSEL][DPOS];
__device__ int d_done;

// ---------------------------------------------------------------------------
// Threefry-2x32 (20 rounds), JAX partitionable layout:
//   bits[f] = o0 ^ o1 of E(key=(0,42), ctr=(hi=0, lo=f))
// ---------------------------------------------------------------------------
__device__ __forceinline__ uint32_t threefry_bits(uint32_t ctr) {
    const uint32_t K0 = 0u;
    const uint32_t K1 = 42u;
    const uint32_t K2 = 0x1BD11BDAu ^ K0 ^ K1;
    uint32_t x0 = K0;
    uint32_t x1 = ctr + K1;
#define TFR(r) { x0 += x1; x1 = __funnelshift_l(x1, x1, (r)); x1 ^= x0; }
    TFR(13) TFR(15) TFR(26) TFR(6)
    x0 += K1; x1 += K2 + 1u;
    TFR(17) TFR(29) TFR(16) TFR(24)
    x0 += K2; x1 += K0 + 2u;
    TFR(13) TFR(15) TFR(26) TFR(6)
    x0 += K0; x1 += K1 + 3u;
    TFR(17) TFR(29) TFR(16) TFR(24)
    x0 += K1; x1 += K2 + 4u;
    TFR(13) TFR(15) TFR(26) TFR(6)
    x0 += K2; x1 += K0 + 5u;
#undef TFR
    return x0 ^ x1;
}

__device__ __forceinline__ float jax_normal(uint32_t f) {
    uint32_t bits = threefry_bits(f);
    float fl = __uint_as_float((bits >> 9) | 0x3f800000u) - 1.0f;  // [0,1)
    const float lo = -0.99999994f;
    float u = fl * 2.0f + lo;
    u = fmaxf(lo, u);
    return __uint_as_float(0x3fb504f3u) * erfinvf(u);   // sqrt(2)*erfinv
}

// monotone float -> sortable u32 (strictly order-preserving)
__device__ __forceinline__ uint32_t fkey(float v) {
    uint32_t u = __float_as_uint(v);
    return u ^ (uint32_t)(((int)u >> 31) | 0x80000000);
}

// ---------------------------------------------------------------------------
// Kernel 1: perturbed top-K counting; fused normalization; 1 sample/warp,
// REDUX-based selection. grid = (125, NB), block = 128 (4 warps).
// ---------------------------------------------------------------------------
__global__ void indicator_kernel(const float* __restrict__ scores) {
    __shared__ float s_sh[DPOS];
    __shared__ float red[64];
    int b = blockIdx.y;
    int t = threadIdx.x;
    int warp = t >> 5, lane = t & 31;

    // per-batch min/max normalize (redundant per block; trivial)
    float v0 = __ldg(scores + b * DPOS + t);
    float v1 = __ldg(scores + b * DPOS + 128 + t);
    float mn = fminf(v0, v1), mx = fmaxf(v0, v1);
#pragma unroll
    for (int off = 16; off; off >>= 1) {
        mn = fminf(mn, __shfl_down_sync(0xffffffffu, mn, off));
        mx = fmaxf(mx, __shfl_down_sync(0xffffffffu, mx, off));
    }
    if (lane == 0) { red[warp] = mn; red[32 + warp] = mx; }
    __syncthreads();
    if (t == 0) {
        float m0 = red[0], m1 = red[32];
#pragma unroll
        for (int j = 1; j < 4; j++) { m0 = fminf(m0, red[j]); m1 = fmaxf(m1, red[32 + j]); }
        red[0] = m0; red[32] = m1;
    }
    __syncthreads();
    mn = red[0]; mx = red[32];
    float den = (mx - mn) + 1e-5f;
    s_sh[t]       = __fdiv_rn(v0 - mn, den);
    s_sh[t + 128] = __fdiv_rn(v1 - mn, den);
    __syncthreads();

    int sample = blockIdx.x * 4 + warp;            // 0..499
    uint32_t base = (uint32_t)((b * NSAMP + sample) * DPOS);

    uint32_t ka[8];
#pragma unroll
    for (int j = 0; j < 8; j++) {
        int pos = j * 32 + lane;
        float z = jax_normal(base + (uint32_t)pos);
        ka[j] = fkey(__fadd_rn(s_sh[pos], __fmul_rn(z, 0.05f)));
    }

    int sel = 0;
    for (int it = 0; it < KSEL; it++) {
        uint32_t bk = 0u;
        int bp = 0x7fffffff;
#pragma unroll
        for (int j = 0; j < 8; j++) {
            int pos = j * 32 + lane;
            if (ka[j] > bk) { bk = ka[j]; bp = pos; }
        }
        uint32_t m = __reduce_max_sync(0xffffffffu, bk);
        unsigned cand = (bk == m) ? (unsigned)bp : 0x7fffffffu;
        int w = (int)__reduce_min_sync(0xffffffffu, cand);
        int sj = w >> 5;
        if (lane == (w & 31)) {
#pragma unroll
            for (int j = 0; j < 8; j++) if (j == sj) ka[j] = 0u;
        }
        if (lane == it) sel = w;
    }

    // rank = index order among the 16 selections
    int r = 0;
#pragma unroll
    for (int j = 0; j < KSEL; j++) {
        int o = __shfl_sync(0xffffffffu, sel, j);
        if (o < sel) r++;
    }
    if (lane < KSEL) atomicAdd(&d_counts[b][r][sel], 1);
}

// ---------------------------------------------------------------------------
// Kernel 2 (fused build+assemble): each block derives its batch's 4 k-block
// sublists from d_counts into smem (deterministic two-half ballot
// compaction), then accumulates patches. The globally-last block zeroes
// d_counts and resets d_done. grid = (32 pt, 3 c, 8 b), block = 128.
// ---------------------------------------------------------------------------
__device__ __forceinline__ ull fma2(ull a, ull b, ull c) {
    ull d;
    asm("fma.rn.f32x2 %0, %1, %2, %3;" : "=l"(d) : "l"(a), "l"(b), "l"(c));
    return d;
}

__device__ __forceinline__ ull dup2(float w) {
    uint32_t wb = __float_as_uint(w);
    return ((ull)wb << 32) | (ull)wb;
}

__global__ void __launch_bounds__(128) assemble_kernel(const float* __restrict__ x,
                                                       float* __restrict__ out) {
    __shared__ int s_off[NKB + 1];
    __shared__ int s_pos[NKB * DPOS];
    __shared__ alignas(16) ull s_wt[NKB * DPOS][KPB];
    __shared__ int s_wcnt[4];
    __shared__ int s_base;
    __shared__ int s_last;

    int pt = blockIdx.x;          // 0..31
    int c  = blockIdx.y;
    int b  = blockIdx.z;
    int t  = threadIdx.x;
    int warp = t >> 5, lane = t & 31;

    // ---- stage per-position counts for positions t and t+128 ----
    int cntA[KSEL], cntB[KSEL];
#pragma unroll
    for (int k = 0; k < KSEL; k++) {
        cntA[k] = d_counts[b][k][t];
        cntB[k] = d_counts[b][k][t + 128];
    }
    int flatA = (t >> 4) * 65536 + (t & 15) * 64;
    int flatB = flatA + 8 * 65536;     // position t+128: ii += 8, same iw
    if (t == 0) s_base = 0;
    __syncthreads();

    const float r500 = 1.0f / 500.0f;

    // ---- deterministic compaction: per kblock, half A (pos 0..127) then
    //      half B (pos 128..255); order preserved => bit-stable sums ----
#pragma unroll
    for (int kb = 0; kb < NKB; kb++) {
#pragma unroll
        for (int h = 0; h < 2; h++) {
            const int* cnt = (h == 0) ? cntA : cntB;
            int flat = (h == 0) ? flatA : flatB;
            int any = cnt[4 * kb] | cnt[4 * kb + 1] | cnt[4 * kb + 2] | cnt[4 * kb + 3];
            unsigned m = __ballot_sync(0xffffffffu, any != 0);
            if (lane == 0) s_wcnt[warp] = __popc(m);
            __syncthreads();                       // wcnt + prior s_base visible
            int basec = 0, ntot = 0;
#pragma unroll
            for (int wj = 0; wj < 4; wj++) {
                int wc = s_wcnt[wj];
                if (wj < warp) basec += wc;
                ntot += wc;
            }
            int base = s_base;
            if (h == 0 && t == 0) s_off[kb] = base;
            if (any) {
                int slot = base + basec + __popc(m & ((1u << lane) - 1u));
                s_pos[slot] = flat;
#pragma unroll
                for (int j = 0; j < KPB; j++)
                    s_wt[slot][j] = dup2((float)cnt[4 * kb + j] * r500);
            }
            __syncthreads();                       // everyone consumed s_base
            if (t == 0) s_base = base + ntot;
        }
    }
    __syncthreads();
    if (t == 0) {
        s_off[NKB] = s_base;
        // all count reads in this block are done -> signal completion
        s_last = (atomicAdd(&d_done, 1) == NBLK - 1) ? 1 : 0;
    }
    __syncthreads();

    // ---- main accumulation ----
    int qt = t & 63;              // q pair: q = 2qt, 2qt+1
    int pr = t >> 6;              // 0..1
    int p0 = pt * 4 + pr * 2;     // rows p0, p0+1
    int qc = 2 * qt - 32;         // window col offset (even)
    int pc0 = p0 - 32;

    const float* xb = x + ((size_t)(b * NCH + c) << 20);

#pragma unroll
    for (int kb = 0; kb < NKB; kb++) {
        int e    = s_off[kb];
        int eend = s_off[kb + 1];

        ull acc0[KPB], acc1[KPB];
#pragma unroll
        for (int j = 0; j < KPB; j++) { acc0[j] = 0ull; acc1[j] = 0ull; }

#pragma unroll 1
        for (; e + 2 <= eend; e += 2) {
            int fA = s_pos[e], fB = s_pos[e + 1];
            int colA = (fA & 1023) + qc, colB = (fB & 1023) + qc;
            int rwA0 = (fA >> 10) + pc0, rwB0 = (fB >> 10) + pc0;
            bool cokA = (unsigned)colA < 1024u;
            bool cokB = (unsigned)colB < 1024u;
            ull vA0 = 0ull, vA1 = 0ull, vB0 = 0ull, vB1 = 0ull;
            const float* pa = xb + ((size_t)rwA0 << 10) + colA;
            const float* pb = xb + ((size_t)rwB0 << 10) + colB;
            if (cokA && (unsigned)rwA0 < 1024u)       vA0 = *(const ull*)pa;
            if (cokA && (unsigned)(rwA0 + 1) < 1024u) vA1 = *(const ull*)(pa + IMG);
            if (cokB && (unsigned)rwB0 < 1024u)       vB0 = *(const ull*)pb;
            if (cokB && (unsigned)(rwB0 + 1) < 1024u) vB1 = *(const ull*)(pb + IMG);
            ulonglong2 wA0 = *(const ulonglong2*)&s_wt[e][0];
            ulonglong2 wA1 = *(const ulonglong2*)&s_wt[e][2];
            ulonglong2 wB0 = *(const ulonglong2*)&s_wt[e + 1][0];
            ulonglong2 wB1 = *(const ulonglong2*)&s_wt[e + 1][2];
            acc0[0] = fma2(wA0.x, vA0, acc0[0]); acc1[0] = fma2(wA0.x, vA1, acc1[0]);
            acc0[1] = fma2(wA0.y, vA0, acc0[1]); acc1[1] = fma2(wA0.y, vA1, acc1[1]);
            acc0[2] = fma2(wA1.x, vA0, acc0[2]); acc1[2] = fma2(wA1.x, vA1, acc1[2]);
            acc0[3] = fma2(wA1.y, vA0, acc0[3]); acc1[3] = fma2(wA1.y, vA1, acc1[3]);
            acc0[0] = fma2(wB0.x, vB0, acc0[0]); acc1[0] = fma2(wB0.x, vB1, acc1[0]);
            acc0[1] = fma2(wB0.y, vB0, acc0[1]); acc1[1] = fma2(wB0.y, vB1, acc1[1]);
            acc0[2] = fma2(wB1.x, vB0, acc0[2]); acc1[2] = fma2(wB1.x, vB1, acc1[2]);
            acc0[3] = fma2(wB1.y, vB0, acc0[3]); acc1[3] = fma2(wB1.y, vB1, acc1[3]);
        }
        for (; e < eend; e++) {
            int f = s_pos[e];
            int col = (f & 1023) + qc;
            int rw0 = (f >> 10) + pc0;
            bool cok = (unsigned)col < 1024u;
            ull v0 = 0ull, v1 = 0ull;
            const float* pa = xb + ((size_t)rw0 << 10) + col;
            if (cok && (unsigned)rw0 < 1024u)       v0 = *(const ull*)pa;
            if (cok && (unsigned)(rw0 + 1) < 1024u) v1 = *(const ull*)(pa + IMG);
            ulonglong2 w0 = *(const ulonglong2*)&s_wt[e][0];
            ulonglong2 w1 = *(const ulonglong2*)&s_wt[e][2];
            acc0[0] = fma2(w0.x, v0, acc0[0]); acc1[0] = fma2(w0.x, v1, acc1[0]);
            acc0[1] = fma2(w0.y, v0, acc0[1]); acc1[1] = fma2(w0.y, v1, acc1[1]);
            acc0[2] = fma2(w1.x, v0, acc0[2]); acc1[2] = fma2(w1.x, v1, acc1[2]);
            acc0[3] = fma2(w1.y, v0, acc0[3]); acc1[3] = fma2(w1.y, v1, acc1[3]);
        }

#pragma unroll
        for (int j = 0; j < KPB; j++) {
            int k = kb * KPB + j;
            float* op = out + (((size_t)((b * KSEL + k) * NCH + c)) << 14)
                            + ((size_t)p0 << 7) + 2 * qt;
            *(ull*)op           = acc0[j];
            *(ull*)(op + PATCH) = acc1[j];
        }
    }

    // ---- last block restores d_counts (all blocks' reads completed) ----
    if (s_last) {
        int4 z4 = make_int4(0, 0, 0, 0);
        int4* cp = (int4*)&d_counts[0][0][0];
        const int n4 = NB * KSEL * DPOS / 4;     // 8192 int4
#pragma unroll 1
        for (int i = t; i < n4; i += 128) cp[i] = z4;
        if (t == 0) d_done = 0;
    }
}

// ---------------------------------------------------------------------------
extern "C" void kernel_launch(void* const* d_in, const int* in_sizes, int n_in,
                              void* d_out, int out_size) {
    const float* x      = (const float*)d_in[0];
    const float* scores = (const float*)d_in[1];
    if (n_in >= 2 && in_sizes[0] == NB * HGRID * WGRID) {
        const float* tmp = x; x = scores; scores = tmp;
    }
    float* out = (float*)d_out;

    indicator_kernel<<<dim3(125, NB), 128>>>(scores);
    assemble_kernel<<<dim3(32, NCH, NB), 128>>>(x, out);
}